// round 4
// baseline (speedup 1.0000x reference)
#include <cuda_runtime.h>
#include <math_constants.h>

// Shape fixed by dataset: pred [B,M,3] f32, gt [B,N,3] f32, values ~uniform [0,1]^3.
constexpr int B = 4;
constexpr int M = 8192;
constexpr int N = 8192;

constexpr int G  = 16;          // grid cells per dimension
constexpr int NC = G * G * G;   // 4096 cells per batch
constexpr int REDB = 32;

// -------- scratch (__device__ globals; no allocation allowed) --------
__device__ float4 g_bbox[B];          // (bmin.x, bmin.y, bmin.z, h)
__device__ int    g_count[B * NC];    // points per cell
__device__ int    g_start[B * NC];    // exclusive prefix (cell list start)
__device__ int    g_cursor[B * NC];   // scatter cursors (copy of g_start)
__device__ float4 g_pts[B * N];       // gt points sorted by cell
__device__ float  g_d[B * M];         // per-query nearest distance
__device__ float  g_partial[REDB];

// ---------------------------------------------------------------------
// 1) Per-batch bbox (min/max over gt) + zero the cell counters.
//    grid = B blocks of 1024 threads.
__global__ void bbox_kernel(const float* __restrict__ gt) {
    const int b = blockIdx.x, tid = threadIdx.x;

    for (int i = tid; i < NC; i += 1024) g_count[b * NC + i] = 0;

    float mn[3] = { CUDART_INF_F,  CUDART_INF_F,  CUDART_INF_F};
    float mx[3] = {-CUDART_INF_F, -CUDART_INF_F, -CUDART_INF_F};
    const float* src = gt + (size_t)b * N * 3;
    for (int i = tid; i < N; i += 1024) {
        #pragma unroll
        for (int d = 0; d < 3; d++) {
            float v = src[3 * i + d];
            mn[d] = fminf(mn[d], v);
            mx[d] = fmaxf(mx[d], v);
        }
    }
    // warp reduce
    #pragma unroll
    for (int o = 16; o > 0; o >>= 1) {
        #pragma unroll
        for (int d = 0; d < 3; d++) {
            mn[d] = fminf(mn[d], __shfl_xor_sync(0xffffffffu, mn[d], o));
            mx[d] = fmaxf(mx[d], __shfl_xor_sync(0xffffffffu, mx[d], o));
        }
    }
    __shared__ float smn[3][32], smx[3][32];
    const int wid = tid >> 5, lid = tid & 31;
    if (lid == 0)
        #pragma unroll
        for (int d = 0; d < 3; d++) { smn[d][wid] = mn[d]; smx[d][wid] = mx[d]; }
    __syncthreads();
    if (wid == 0) {
        #pragma unroll
        for (int d = 0; d < 3; d++) { mn[d] = smn[d][lid]; mx[d] = smx[d][lid]; }
        #pragma unroll
        for (int o = 16; o > 0; o >>= 1) {
            #pragma unroll
            for (int d = 0; d < 3; d++) {
                mn[d] = fminf(mn[d], __shfl_xor_sync(0xffffffffu, mn[d], o));
                mx[d] = fmaxf(mx[d], __shfl_xor_sync(0xffffffffu, mx[d], o));
            }
        }
        if (lid == 0) {
            float ext = fmaxf(fmaxf(mx[0] - mn[0], mx[1] - mn[1]), mx[2] - mn[2]);
            float h = ext / (float)G;
            if (!(h > 0.0f)) h = 1.0f;   // degenerate: everything lands in cell 0
            g_bbox[b] = make_float4(mn[0], mn[1], mn[2], h);
        }
    }
}

__device__ __forceinline__ int cell_coord(float v, float bmin, float invh) {
    int c = (int)((v - bmin) * invh);
    return min(G - 1, max(0, c));
}

// 2) Histogram: count gt points per cell.  grid = B*N/256 blocks of 256.
__global__ void hist_kernel(const float* __restrict__ gt) {
    int i = blockIdx.x * 256 + threadIdx.x;           // global gt index
    int b = i / N;
    float4 bb = g_bbox[b];
    float invh = 1.0f / bb.w;
    float x = gt[3 * i], y = gt[3 * i + 1], z = gt[3 * i + 2];
    int cx = cell_coord(x, bb.x, invh);
    int cy = cell_coord(y, bb.y, invh);
    int cz = cell_coord(z, bb.z, invh);
    atomicAdd(&g_count[b * NC + (cz * G + cy) * G + cx], 1);
}

// 3) Exclusive prefix sum of the 4096 counts per batch.  grid = B, block 1024.
__global__ void scan_kernel() {
    const int b = blockIdx.x, tid = threadIdx.x;
    const int base = b * NC;
    int v[4];
    #pragma unroll
    for (int t = 0; t < 4; t++) v[t] = g_count[base + tid * 4 + t];
    int tsum = v[0] + v[1] + v[2] + v[3];

    __shared__ int s[1024];
    s[tid] = tsum;
    __syncthreads();
    for (int off = 1; off < 1024; off <<= 1) {
        int a = (tid >= off) ? s[tid - off] : 0;
        __syncthreads();
        s[tid] += a;
        __syncthreads();
    }
    int run = s[tid] - tsum;   // exclusive
    #pragma unroll
    for (int t = 0; t < 4; t++) {
        g_start[base + tid * 4 + t]  = run;
        g_cursor[base + tid * 4 + t] = run;
        run += v[t];
    }
}

// 4) Scatter gt points into cell-sorted order.  grid = B*N/256 blocks of 256.
__global__ void scatter_kernel(const float* __restrict__ gt) {
    int i = blockIdx.x * 256 + threadIdx.x;
    int b = i / N;
    float4 bb = g_bbox[b];
    float invh = 1.0f / bb.w;
    float x = gt[3 * i], y = gt[3 * i + 1], z = gt[3 * i + 2];
    int cx = cell_coord(x, bb.x, invh);
    int cy = cell_coord(y, bb.y, invh);
    int cz = cell_coord(z, bb.z, invh);
    int pos = atomicAdd(&g_cursor[b * NC + (cz * G + cy) * G + cx], 1);
    g_pts[b * N + pos] = make_float4(x, y, z, 0.0f);
}

// 5) Query: expanding-ring exact nearest neighbor.  grid = B*M/256 of 256.
__global__ __launch_bounds__(256) void query_kernel(const float* __restrict__ pred) {
    int i = blockIdx.x * 256 + threadIdx.x;           // global pred index
    int b = i / M;
    float4 bb = g_bbox[b];
    float invh = 1.0f / bb.w;

    float qx = pred[3 * i], qy = pred[3 * i + 1], qz = pred[3 * i + 2];
    int cx = cell_coord(qx, bb.x, invh);
    int cy = cell_coord(qy, bb.y, invh);
    int cz = cell_coord(qz, bb.z, invh);

    const float4* __restrict__ pts  = g_pts  + b * N;
    const int*    __restrict__ cst  = g_start + b * NC;
    const int*    __restrict__ ccnt = g_count + b * NC;

    float best = CUDART_INF_F;

    #define SCAN_CELL(XX, YY, ZZ) do {                                        \
        int c = ((ZZ) * G + (YY)) * G + (XX);                                 \
        int s0 = cst[c], e0 = s0 + ccnt[c];                                   \
        for (int t = s0; t < e0; t++) {                                       \
            float4 p = pts[t];                                                \
            float dx = qx - p.x, dy = qy - p.y, dz = qz - p.z;                \
            best = fminf(best, fmaf(dx, dx, fmaf(dy, dy, dz * dz)));          \
        }                                                                     \
    } while (0)

    for (int R = 0; R < G; R++) {
        int x0 = max(cx - R, 0), x1 = min(cx + R, G - 1);
        int y0 = max(cy - R, 0), y1 = min(cy + R, G - 1);
        int z0 = max(cz - R, 0), z1 = min(cz + R, G - 1);
        for (int zz = z0; zz <= z1; zz++) {
            bool ze = (zz == cz - R) || (zz == cz + R);
            for (int yy = y0; yy <= y1; yy++) {
                bool edge = ze || (yy == cy - R) || (yy == cy + R);
                if (edge) {
                    for (int xx = x0; xx <= x1; xx++) SCAN_CELL(xx, yy, zz);
                } else {
                    int xa = cx - R, xb = cx + R;       // shell endpoints only
                    if (xa >= 0)            SCAN_CELL(xa, yy, zz);
                    if (xb <= G - 1 && xb != xa) SCAN_CELL(xb, yy, zz);
                }
            }
        }
        // After rings 0..R, any unscanned point is >= R*h away.
        float bound = (float)R * bb.w;
        if (best <= bound * bound) break;
    }
    #undef SCAN_CELL

    g_d[i] = sqrtf(fmaxf(best, 0.0f));
}

// 6) Deterministic two-stage mean.
__global__ void reduce_partial_kernel() {
    __shared__ float ssum[1024];
    const int tid = threadIdx.x;
    ssum[tid] = g_d[blockIdx.x * 1024 + tid];   // 32 * 1024 = 32768 exactly
    __syncthreads();
    for (int s = 512; s > 0; s >>= 1) {
        if (tid < s) ssum[tid] += ssum[tid + s];
        __syncthreads();
    }
    if (tid == 0) g_partial[blockIdx.x] = ssum[0];
}

__global__ void reduce_final_kernel(float* __restrict__ out, int out_size) {
    float sum = 0.0f;
    #pragma unroll
    for (int i = 0; i < REDB; i++) sum += g_partial[i];
    float val = sum * (1.0f / (float)(B * M));   // LOSS_WEIGHT = 1.0
    for (int i = threadIdx.x; i < out_size; i += 32) out[i] = val;
}

extern "C" void kernel_launch(void* const* d_in, const int* in_sizes, int n_in,
                              void* d_out, int out_size) {
    const float* pred = (const float*)d_in[0];  // [B, M, 3]
    const float* gt   = (const float*)d_in[1];  // [B, N, 3]
    float* out = (float*)d_out;

    bbox_kernel<<<B, 1024>>>(gt);
    hist_kernel<<<B * N / 256, 256>>>(gt);
    scan_kernel<<<B, 1024>>>();
    scatter_kernel<<<B * N / 256, 256>>>(gt);
    query_kernel<<<B * M / 256, 256>>>(pred);
    reduce_partial_kernel<<<REDB, 1024>>>();
    reduce_final_kernel<<<1, 32>>>(out, out_size);
}

// round 5
// speedup vs baseline: 1.7175x; 1.7175x over previous
#include <cuda_runtime.h>
#include <math_constants.h>

// Shape fixed by dataset: pred [B,M,3] f32, gt [B,N,3] f32 (~uniform [0,1]^3).
constexpr int B = 4;
constexpr int M = 8192;
constexpr int N = 8192;

constexpr int G  = 16;          // grid cells per dimension
constexpr int NC = G * G * G;   // 4096 cells per batch

constexpr int QTPB   = 1024;                 // query block: 32 warps = 32 queries
constexpr int QBLK   = (B * M) / 32 / (QTPB / 32) * 1;  // computed below; keep literal
constexpr int NQBLK  = (B * M) / (QTPB / 32);            // 1024 blocks

// -------- scratch (__device__ globals; no allocation allowed) --------
__device__ float4 g_bbox[B];            // (bmin.x, bmin.y, bmin.z, h)
__device__ int2   g_cell[B * NC];       // (start, count) per cell
__device__ float4 g_pts[B * N];         // gt points sorted by cell
__device__ float  g_partial[NQBLK];     // per-block partial sums of nn distances

__device__ __forceinline__ int cell_coord(float v, float bmin, float invh) {
    int c = (int)((v - bmin) * invh);
    return min(G - 1, max(0, c));
}

// =====================================================================
// 1) Fused grid build: bbox + histogram + scan + scatter. One block/batch.
__global__ __launch_bounds__(1024) void build_kernel(const float* __restrict__ gt) {
    const int b = blockIdx.x, tid = threadIdx.x;

    __shared__ int    scount[NC];    // 16 KB
    __shared__ int    scursor[NC];   // 16 KB
    __shared__ int    sscan[1024];   // 4 KB
    __shared__ float  sred[6][32];
    __shared__ float4 sbb;

    // ---- load this batch's 8192 points, 8 per thread (coalesced) ----
    float px[8], py[8], pz[8];
    const float* src = gt + (size_t)b * N * 3;
    #pragma unroll
    for (int k = 0; k < 8; k++) {
        int i = tid + k * 1024;
        px[k] = src[3 * i + 0];
        py[k] = src[3 * i + 1];
        pz[k] = src[3 * i + 2];
    }

    // ---- bbox reduction ----
    float mnx = CUDART_INF_F, mny = CUDART_INF_F, mnz = CUDART_INF_F;
    float mxx = -CUDART_INF_F, mxy = -CUDART_INF_F, mxz = -CUDART_INF_F;
    #pragma unroll
    for (int k = 0; k < 8; k++) {
        mnx = fminf(mnx, px[k]); mxx = fmaxf(mxx, px[k]);
        mny = fminf(mny, py[k]); mxy = fmaxf(mxy, py[k]);
        mnz = fminf(mnz, pz[k]); mxz = fmaxf(mxz, pz[k]);
    }
    #pragma unroll
    for (int o = 16; o > 0; o >>= 1) {
        mnx = fminf(mnx, __shfl_xor_sync(~0u, mnx, o));
        mny = fminf(mny, __shfl_xor_sync(~0u, mny, o));
        mnz = fminf(mnz, __shfl_xor_sync(~0u, mnz, o));
        mxx = fmaxf(mxx, __shfl_xor_sync(~0u, mxx, o));
        mxy = fmaxf(mxy, __shfl_xor_sync(~0u, mxy, o));
        mxz = fmaxf(mxz, __shfl_xor_sync(~0u, mxz, o));
    }
    const int wid = tid >> 5, lid = tid & 31;
    if (lid == 0) {
        sred[0][wid] = mnx; sred[1][wid] = mny; sred[2][wid] = mnz;
        sred[3][wid] = mxx; sred[4][wid] = mxy; sred[5][wid] = mxz;
    }
    __syncthreads();
    if (wid == 0) {
        mnx = sred[0][lid]; mny = sred[1][lid]; mnz = sred[2][lid];
        mxx = sred[3][lid]; mxy = sred[4][lid]; mxz = sred[5][lid];
        #pragma unroll
        for (int o = 16; o > 0; o >>= 1) {
            mnx = fminf(mnx, __shfl_xor_sync(~0u, mnx, o));
            mny = fminf(mny, __shfl_xor_sync(~0u, mny, o));
            mnz = fminf(mnz, __shfl_xor_sync(~0u, mnz, o));
            mxx = fmaxf(mxx, __shfl_xor_sync(~0u, mxx, o));
            mxy = fmaxf(mxy, __shfl_xor_sync(~0u, mxy, o));
            mxz = fmaxf(mxz, __shfl_xor_sync(~0u, mxz, o));
        }
        if (lid == 0) {
            float ext = fmaxf(fmaxf(mxx - mnx, mxy - mny), mxz - mnz);
            float h = ext / (float)G;
            if (!(h > 0.0f)) h = 1.0f;
            sbb = make_float4(mnx, mny, mnz, h);
            g_bbox[b] = sbb;
        }
    }

    // ---- zero histogram ----
    #pragma unroll
    for (int t = 0; t < 4; t++) scount[tid * 4 + t] = 0;
    __syncthreads();

    const float4 bb = sbb;
    const float invh = 1.0f / bb.w;

    // ---- histogram ----
    int cidx[8];
    #pragma unroll
    for (int k = 0; k < 8; k++) {
        int cx = cell_coord(px[k], bb.x, invh);
        int cy = cell_coord(py[k], bb.y, invh);
        int cz = cell_coord(pz[k], bb.z, invh);
        cidx[k] = (cz * G + cy) * G + cx;
        atomicAdd(&scount[cidx[k]], 1);
    }
    __syncthreads();

    // ---- exclusive scan over 4096 counts (4 per thread + Hillis-Steele) ----
    int v[4];
    #pragma unroll
    for (int t = 0; t < 4; t++) v[t] = scount[tid * 4 + t];
    int tsum = v[0] + v[1] + v[2] + v[3];
    sscan[tid] = tsum;
    __syncthreads();
    for (int off = 1; off < 1024; off <<= 1) {
        int a = (tid >= off) ? sscan[tid - off] : 0;
        __syncthreads();
        sscan[tid] += a;
        __syncthreads();
    }
    int run = sscan[tid] - tsum;  // exclusive
    #pragma unroll
    for (int t = 0; t < 4; t++) {
        int c = tid * 4 + t;
        g_cell[b * NC + c] = make_int2(run, v[t]);
        scursor[c] = run;
        run += v[t];
    }
    __syncthreads();

    // ---- scatter points into cell-sorted order ----
    float4* dst = g_pts + (size_t)b * N;
    #pragma unroll
    for (int k = 0; k < 8; k++) {
        int pos = atomicAdd(&scursor[cidx[k]], 1);
        dst[pos] = make_float4(px[k], py[k], pz[k], 0.0f);
    }
}

// =====================================================================
// 2) Warp-cooperative exact NN query + in-kernel partial mean.
//    One warp per query; lanes 0..26 scan the 3x3x3 neighborhood.
__global__ __launch_bounds__(QTPB) void query_kernel(const float* __restrict__ pred) {
    __shared__ float ssum[32];

    const int lane = threadIdx.x & 31;
    const int warp = threadIdx.x >> 5;
    const int q    = blockIdx.x * 32 + warp;        // global query id in [0, B*M)
    const int b    = q >> 13;                       // q / 8192

    const float4 bb = g_bbox[b];
    const float invh = 1.0f / bb.w;
    const float h = bb.w;

    const float qx = pred[3 * q + 0];
    const float qy = pred[3 * q + 1];
    const float qz = pred[3 * q + 2];

    const int cx = cell_coord(qx, bb.x, invh);
    const int cy = cell_coord(qy, bb.y, invh);
    const int cz = cell_coord(qz, bb.z, invh);

    const int2*   __restrict__ cell = g_cell + b * NC;
    const float4* __restrict__ pts  = g_pts  + (size_t)b * N;

    float best = CUDART_INF_F;

    // Rings 0+1: 27 cells, one per lane.
    if (lane < 27) {
        int dx = lane % 3 - 1, dy = (lane / 3) % 3 - 1, dz = lane / 9 - 1;
        int xx = cx + dx, yy = cy + dy, zz = cz + dz;
        if (xx >= 0 && xx < G && yy >= 0 && yy < G && zz >= 0 && zz < G) {
            int2 sc = cell[(zz * G + yy) * G + xx];
            for (int t = sc.x; t < sc.x + sc.y; t++) {
                float4 p = pts[t];
                float ddx = qx - p.x, ddy = qy - p.y, ddz = qz - p.z;
                best = fminf(best, fmaf(ddx, ddx, fmaf(ddy, ddy, ddz * ddz)));
            }
        }
    }
    #pragma unroll
    for (int o = 16; o > 0; o >>= 1)
        best = fminf(best, __shfl_xor_sync(~0u, best, o));

    // Rare fallback: expand Chebyshev rings until bound certifies the min.
    // After scanning rings 0..R, any unscanned point is >= R*h away.
    int R = 1;
    while (best > (float)R * h * (float)R * h && R < G) {
        R++;
        int side = 2 * R + 1;
        int total = side * side * side;
        float lb = CUDART_INF_F;
        for (int s = lane; s < total; s += 32) {
            int dz = s / (side * side) - R;
            int dy = (s / side) % side - R;
            int dx = s % side - R;
            if (max(abs(dx), max(abs(dy), abs(dz))) != R) continue;  // shell only
            int xx = cx + dx, yy = cy + dy, zz = cz + dz;
            if (xx < 0 || xx >= G || yy < 0 || yy >= G || zz < 0 || zz >= G) continue;
            int2 sc = cell[(zz * G + yy) * G + xx];
            for (int t = sc.x; t < sc.x + sc.y; t++) {
                float4 p = pts[t];
                float ddx = qx - p.x, ddy = qy - p.y, ddz = qz - p.z;
                lb = fminf(lb, fmaf(ddx, ddx, fmaf(ddy, ddy, ddz * ddz)));
            }
        }
        #pragma unroll
        for (int o = 16; o > 0; o >>= 1)
            lb = fminf(lb, __shfl_xor_sync(~0u, lb, o));
        best = fminf(best, lb);
    }

    // Per-block deterministic partial sum of sqrt(best).
    if (lane == 0) ssum[warp] = sqrtf(fmaxf(best, 0.0f));
    __syncthreads();
    if (warp == 0) {
        float v = ssum[lane];
        #pragma unroll
        for (int o = 16; o > 0; o >>= 1)
            v += __shfl_xor_sync(~0u, v, o);
        if (lane == 0) g_partial[blockIdx.x] = v;
    }
}

// =====================================================================
// 3) Final mean over NQBLK (=1024) partials. Single block, fixed tree.
__global__ __launch_bounds__(1024) void reduce_final_kernel(float* __restrict__ out,
                                                            int out_size) {
    __shared__ float s[1024];
    s[threadIdx.x] = g_partial[threadIdx.x];
    __syncthreads();
    for (int o = 512; o > 0; o >>= 1) {
        if (threadIdx.x < o) s[threadIdx.x] += s[threadIdx.x + o];
        __syncthreads();
    }
    float val = s[0] * (1.0f / (float)(B * M));  // LOSS_WEIGHT = 1.0
    for (int i = threadIdx.x; i < out_size; i += 1024) out[i] = val;
}

extern "C" void kernel_launch(void* const* d_in, const int* in_sizes, int n_in,
                              void* d_out, int out_size) {
    const float* pred = (const float*)d_in[0];  // [B, M, 3]
    const float* gt   = (const float*)d_in[1];  // [B, N, 3]
    float* out = (float*)d_out;

    build_kernel<<<B, 1024>>>(gt);
    query_kernel<<<NQBLK, QTPB>>>(pred);       // 1024 blocks x 32 warps
    reduce_final_kernel<<<1, 1024>>>(out, out_size);
}

// round 7
// speedup vs baseline: 2.1452x; 1.2490x over previous
#include <cuda_runtime.h>
#include <math_constants.h>

// Shape fixed by dataset: pred [B,M,3] f32, gt [B,N,3] f32 (uniform [0,1]^3).
constexpr int B = 4;
constexpr int M = 8192;
constexpr int N = 8192;

constexpr int G   = 16;           // cells per dimension, fixed [0,1]^3 grid
constexpr int NC  = G * G * G;    // 4096 cells per batch
constexpr int CAP = 16;           // bucket capacity (Poisson(2) => overflow ~never)

constexpr int QTPB  = 1024;                  // 32 warps = 32 queries per block
constexpr int NQBLK = (B * M) / (QTPB / 32); // 1024 query blocks

// -------- scratch (__device__ globals; zero-initialized at module load) -----
__device__ int    g_cnt[B * NC];        // points per cell (zeroed after each run)
__device__ int    g_ovfn[B];            // overflow counts  (zeroed after each run)
__device__ float4 g_buck[B * NC * CAP]; // direct-mapped cell buckets (4 MB)
__device__ float4 g_ovf[B * N];         // overflow points (exactness fallback)
__device__ float  g_partial[NQBLK];     // per-block partial sums
__device__ int    g_done;               // completed-block counter (reset each run)

__device__ __forceinline__ int cc(float v) {
    int c = (int)(v * (float)G);
    return min(G - 1, max(0, c));
}

// ============================================================================
// 1) Build: fully parallel direct-bucket insert. One thread per gt point.
__global__ __launch_bounds__(256) void build_kernel(const float* __restrict__ gt) {
    int i = blockIdx.x * 256 + threadIdx.x;   // [0, B*N)
    int b = i >> 13;
    float x = gt[3 * i + 0];
    float y = gt[3 * i + 1];
    float z = gt[3 * i + 2];
    int cell = (cc(z) * G + cc(y)) * G + cc(x);
    int pos = atomicAdd(&g_cnt[b * NC + cell], 1);
    if (pos < CAP) {
        g_buck[(b * NC + cell) * CAP + pos] = make_float4(x, y, z, 0.0f);
    } else {
        int o = atomicAdd(&g_ovfn[b], 1);
        g_ovf[b * N + o] = make_float4(x, y, z, 0.0f);
    }
}

// ============================================================================
// 2) Query: warp-cooperative exact NN + fused deterministic final mean.
__global__ __launch_bounds__(QTPB) void query_kernel(const float* __restrict__ pred,
                                                     float* __restrict__ out,
                                                     int out_size) {
    __shared__ float ssum[32];
    __shared__ float sfin[1024];
    __shared__ int   slast;

    const int lane = threadIdx.x & 31;
    const int warp = threadIdx.x >> 5;
    const int q    = blockIdx.x * 32 + warp;   // global query id
    const int b    = q >> 13;
    const float h  = 1.0f / (float)G;

    const float qx = pred[3 * q + 0];
    const float qy = pred[3 * q + 1];
    const float qz = pred[3 * q + 2];

    const int cx = cc(qx), cy = cc(qy), cz = cc(qz);

    const int*    __restrict__ cnt  = g_cnt  + b * NC;
    const float4* __restrict__ buck = g_buck + (size_t)b * NC * CAP;

    float best = CUDART_INF_F;

    // Rings 0+1: the 3x3x3 neighborhood, one cell per lane (lanes 0..26).
    if (lane < 27) {
        int dx = lane % 3 - 1, dy = (lane / 3) % 3 - 1, dz = lane / 9 - 1;
        int xx = cx + dx, yy = cy + dy, zz = cz + dz;
        if (((unsigned)xx < G) & ((unsigned)yy < G) & ((unsigned)zz < G)) {
            int c = (zz * G + yy) * G + xx;
            int n = min(__ldg(cnt + c), CAP);
            const float4* p0 = buck + c * CAP;
            for (int t = 0; t < n; t++) {
                float4 p = __ldg(p0 + t);
                float ddx = qx - p.x, ddy = qy - p.y, ddz = qz - p.z;
                best = fminf(best, fmaf(ddx, ddx, fmaf(ddy, ddy, ddz * ddz)));
            }
        }
    }
    // Overflow list (empty in practice; keeps the algorithm exact).
    {
        const float4* __restrict__ ovf = g_ovf + b * N;
        int ovfn = g_ovfn[b];
        for (int s = lane; s < ovfn; s += 32) {
            float4 p = ovf[s];
            float ddx = qx - p.x, ddy = qy - p.y, ddz = qz - p.z;
            best = fminf(best, fmaf(ddx, ddx, fmaf(ddy, ddy, ddz * ddz)));
        }
    }
    #pragma unroll
    for (int o = 16; o > 0; o >>= 1)
        best = fminf(best, __shfl_xor_sync(~0u, best, o));

    // Rare fallback: expanding Chebyshev rings. After scanning rings 0..R,
    // any unscanned point is >= R*h away (clamped outliers are even farther).
    int R = 1;
    while (best > (float)(R) * h * (float)(R) * h && R < G) {
        R++;
        int side = 2 * R + 1;
        int total = side * side * side;
        float lb = CUDART_INF_F;
        for (int s = lane; s < total; s += 32) {
            int dz = s / (side * side) - R;
            int dy = (s / side) % side - R;
            int dx = s % side - R;
            if (max(abs(dx), max(abs(dy), abs(dz))) != R) continue;  // shell only
            int xx = cx + dx, yy = cy + dy, zz = cz + dz;
            if (xx < 0 || xx >= G || yy < 0 || yy >= G || zz < 0 || zz >= G) continue;
            int c = (zz * G + yy) * G + xx;
            int n = min(__ldg(cnt + c), CAP);
            const float4* p0 = buck + c * CAP;
            for (int t = 0; t < n; t++) {
                float4 p = __ldg(p0 + t);
                float ddx = qx - p.x, ddy = qy - p.y, ddz = qz - p.z;
                lb = fminf(lb, fmaf(ddx, ddx, fmaf(ddy, ddy, ddz * ddz)));
            }
        }
        #pragma unroll
        for (int o = 16; o > 0; o >>= 1)
            lb = fminf(lb, __shfl_xor_sync(~0u, lb, o));
        best = fminf(best, lb);
    }

    // Per-block deterministic partial sum of sqrt(best).
    if (lane == 0) ssum[warp] = sqrtf(fmaxf(best, 0.0f));
    __syncthreads();
    if (warp == 0) {
        float v = ssum[lane];
        #pragma unroll
        for (int o = 16; o > 0; o >>= 1)
            v += __shfl_xor_sync(~0u, v, o);
        if (lane == 0) {
            g_partial[blockIdx.x] = v;
            __threadfence();
            slast = (atomicAdd(&g_done, 1) == NQBLK - 1);
        }
    }
    __syncthreads();

    // Last block: fixed-tree final mean + reset scratch for the next replay.
    if (slast) {
        __threadfence();  // make all g_partial writes visible
        sfin[threadIdx.x] = g_partial[threadIdx.x];   // NQBLK == 1024
        __syncthreads();
        for (int o = 512; o > 0; o >>= 1) {
            if (threadIdx.x < o) sfin[threadIdx.x] += sfin[threadIdx.x + o];
            __syncthreads();
        }
        float val = sfin[0] * (1.0f / (float)(B * M));  // LOSS_WEIGHT = 1.0
        for (int i = threadIdx.x; i < out_size; i += 1024) out[i] = val;

        // Reset counters so every graph replay starts from a clean state.
        #pragma unroll
        for (int t = 0; t < (B * NC) / 1024; t++)
            g_cnt[t * 1024 + threadIdx.x] = 0;
        if (threadIdx.x < B) g_ovfn[threadIdx.x] = 0;
        if (threadIdx.x == 0) g_done = 0;
    }
}

extern "C" void kernel_launch(void* const* d_in, const int* in_sizes, int n_in,
                              void* d_out, int out_size) {
    const float* pred = (const float*)d_in[0];  // [B, M, 3]
    const float* gt   = (const float*)d_in[1];  // [B, N, 3]
    float* out = (float*)d_out;

    build_kernel<<<(B * N) / 256, 256>>>(gt);
    query_kernel<<<NQBLK, QTPB>>>(pred, out, out_size);
}